// round 15
// baseline (speedup 1.0000x reference)
#include <cuda_runtime.h>
#include <cuda_fp16.h>
#include <cstdint>

#define B_ROWS    16384
#define KDIM      192
#define CDIM      256
#define TILE_ROWS 32
#define NTILES    (B_ROWS / TILE_ROWS)   // 512
#define GEMM_GRID 128
#define TILES_PER_CTA (NTILES / GEMM_GRID) // 4
#define GATHER_BLOCKS (B_ROWS / 8)       // 2048

// ===================== scratch =====================
__device__ __half g_X[B_ROWS * KDIM];
__device__ int    g_cnt[NTILES];

// ============================================================
// Kernel A: gather + mean-pool -> g_X fp16 (one warp per row)
//   per-tile completion flags (tile = 4 blocks = 32 rows)
// ============================================================
__global__ void __launch_bounds__(256) gather_kernel(
    const int*   __restrict__ user_input,
    const float* __restrict__ emb,
    const int*   __restrict__ sc_country_idx,
    const float* __restrict__ sc_country_emb,
    const int*   __restrict__ sc_device_idx,
    const float* __restrict__ sc_device_emb,
    const int*   __restrict__ mf_tags_idx,
    const float* __restrict__ mf_tags_emb,
    const int*   __restrict__ mf_history_idx,
    const float* __restrict__ mf_history_emb)
{
    int w    = threadIdx.x >> 5;
    int lane = threadIdx.x & 31;
    int row  = blockIdx.x * 8 + w;

    int u = user_input[row];
    int base = row * KDIM;

    // main embedding: 64 fp32 -> half2
    float2 e = ((const float2*)(emb + (size_t)u * 64))[lane];
    ((__half2*)(g_X + base))[lane] = __floats2half2_rn(e.x, e.y);

    // scalar side features
    int ci = sc_country_idx[u];
    int di = sc_device_idx[u];
    g_X[base + 64 + lane] = __float2half_rn(sc_country_emb[(size_t)ci * 32 + lane]);
    g_X[base + 96 + lane] = __float2half_rn(sc_device_emb[(size_t)di * 32 + lane]);

    // tags: mean over 20
    int ti = (lane < 20) ? mf_tags_idx[(size_t)u * 20 + lane] : 0;
    float tacc = 0.f;
    #pragma unroll
    for (int t = 0; t < 20; t++) {
        int id = __shfl_sync(0xffffffffu, ti, t);
        tacc += mf_tags_emb[(size_t)id * 32 + lane];
    }
    g_X[base + 128 + lane] = __float2half_rn(tacc * (1.f / 20.f));

    // history: mean over 50
    int hA = mf_history_idx[(size_t)u * 50 + lane];
    int hB = (lane < 18) ? mf_history_idx[(size_t)u * 50 + 32 + lane] : 0;
    float a0 = 0.f, a1 = 0.f;
    #pragma unroll
    for (int t = 0; t < 32; t++) {
        int id = __shfl_sync(0xffffffffu, hA, t);
        a0 += mf_history_emb[(size_t)id * 32 + lane];
    }
    #pragma unroll
    for (int t = 0; t < 18; t++) {
        int id = __shfl_sync(0xffffffffu, hB, t);
        a1 += mf_history_emb[(size_t)id * 32 + lane];
    }
    g_X[base + 160 + lane] = __float2half_rn((a0 + a1) * (1.f / 50.f));

    __syncthreads();
    if (threadIdx.x == 0) {
        __threadfence();
        atomicAdd(&g_cnt[blockIdx.x >> 2], 1);
    }
}

// ============================================================
// Kernel B: persistent fp16 HMMA GEMM + bias/relu/LN
//   128 CTAs x 256 thr (8 warps, warp tile 32x32), tile 32x256
//   W converted fp32->fp16 in prologue; per-tile flag spin
// ============================================================
#define GEMM_THREADS 256
#define STRIDE_B  400                       // 192 half = 384B + 16 pad
#define OFF_W     0
#define WSZ       (256 * STRIDE_B)          // 102400
#define OFF_X     WSZ                       // 102400
#define XSZ       (TILE_ROWS * STRIDE_B)    // 12800
#define OFF_PAR   (OFF_X + XSZ)             // 115200
#define OFF_PART  (OFF_PAR + 3 * 256 * 4)   // 118272
#define SMEM_SZ   (OFF_PART + TILE_ROWS * 8 * 8)   // 120320

__device__ __forceinline__ uint32_t smem_u32(const void* p) {
    uint32_t a;
    asm("{ .reg .u64 t; cvta.to.shared.u64 t, %1; cvt.u32.u64 %0, t; }"
        : "=r"(a) : "l"(p));
    return a;
}
__device__ __forceinline__ void cp_async16(uint32_t dst, const void* src) {
    asm volatile("cp.async.cg.shared.global [%0], [%1], 16;"
        :: "r"(dst), "l"(src));
}
#define CP_COMMIT()   asm volatile("cp.async.commit_group;" ::: "memory")
#define CP_WAIT_ALL() asm volatile("cp.async.wait_all;" ::: "memory")

__device__ __forceinline__ void ldsm_x4(uint32_t r[4], uint32_t addr) {
    asm volatile("ldmatrix.sync.aligned.m8n8.x4.shared.b16 {%0,%1,%2,%3}, [%4];"
        : "=r"(r[0]), "=r"(r[1]), "=r"(r[2]), "=r"(r[3]) : "r"(addr));
}
__device__ __forceinline__ void mma16816(float* d, const uint32_t* a,
                                         uint32_t b0, uint32_t b1) {
    asm volatile(
        "mma.sync.aligned.m16n8k16.row.col.f32.f16.f16.f32 "
        "{%0,%1,%2,%3}, {%4,%5,%6,%7}, {%8,%9}, {%0,%1,%2,%3};"
        : "+f"(d[0]), "+f"(d[1]), "+f"(d[2]), "+f"(d[3])
        : "r"(a[0]), "r"(a[1]), "r"(a[2]), "r"(a[3]), "r"(b0), "r"(b1));
}

__device__ __forceinline__ void load_frags(uint32_t xb, uint32_t wb, uint32_t ko,
                                           uint32_t a0[4], uint32_t a1[4],
                                           uint32_t b[2][4]) {
    ldsm_x4(a0, xb + ko);
    ldsm_x4(a1, xb + 16 * STRIDE_B + ko);
    ldsm_x4(b[0], wb + ko);
    ldsm_x4(b[1], wb + 16 * STRIDE_B + ko);
}

__global__ void __launch_bounds__(GEMM_THREADS, 1) gemm_ln_mma_kernel(
    const float* __restrict__ fc_w,
    const float* __restrict__ fc_b,
    const float* __restrict__ ln_g,
    const float* __restrict__ ln_b,
    float*       __restrict__ out)    // [B_ROWS][256]
{
    extern __shared__ __align__(16) char smem[];
    const uint32_t sb = smem_u32(smem);
    const int tid  = threadIdx.x;
    const int lane = tid & 31;
    const int w    = tid >> 5;     // 0..7 : cols w*32..+31

    float*  sPar  = (float*)(smem + OFF_PAR);
    float2* sPart = (float2*)(smem + OFF_PART);   // [32][8] (sum, ss)

    // ---- prologue: convert W fp32 -> fp16 directly into smem ----
    {
        const float4* w4 = (const float4*)fc_w;
        #pragma unroll
        for (int it = 0; it < 48; it++) {            // 12288 / 256
            int i = tid + it * GEMM_THREADS;
            int n = i / 48, q = i - n * 48;          // 48 float4 per channel row
            float4 v = w4[i];
            __half2 p0 = __floats2half2_rn(v.x, v.y);
            __half2 p1 = __floats2half2_rn(v.z, v.w);
            uint2 o;
            o.x = *(uint32_t*)&p0;
            o.y = *(uint32_t*)&p1;
            *(uint2*)(smem + OFF_W + n * STRIDE_B + q * 8) = o;
        }
    }
    if (tid < 256) {
        sPar[tid]       = fc_b[tid];
        sPar[256 + tid] = ln_g[tid];
        sPar[512 + tid] = ln_b[tid];
    }
    __syncthreads();

    const int rk = lane & 15;
    const uint32_t kbyte = (uint32_t)((lane >> 4) << 4);
    const uint32_t xb = sb + OFF_X + (uint32_t)(rk * STRIDE_B) + kbyte;
    const uint32_t wb = sb + OFF_W + (uint32_t)((w * 32 + rk) * STRIDE_B) + kbyte;
    const int c0 = w * 32 + (lane & 3) * 2;

    for (int j = 0; j < TILES_PER_CTA; j++) {
        const int tile   = blockIdx.x + j * GEMM_GRID;
        const int m_base = tile * TILE_ROWS;

        // ---- wait for this tile's gather blocks ----
        if (tid == 0) {
            while (atomicAdd(&g_cnt[tile], 0) < 4) {}
        }
        __syncthreads();

        // ---- stage X tile (32 rows x 24 uint4) ----
        #pragma unroll
        for (int it = 0; it < 3; it++) {             // 768 / 256
            int i = tid + it * GEMM_THREADS;
            int r = i / 24, q = i - r * 24;
            cp_async16(sb + OFF_X + (uint32_t)(r * STRIDE_B + q * 16),
                       g_X + (size_t)(m_base + r) * KDIM + q * 8);
        }
        CP_COMMIT();
        CP_WAIT_ALL();
        __syncthreads();

        float acc[2][4][4];
        #pragma unroll
        for (int a = 0; a < 2; a++)
            #pragma unroll
            for (int b = 0; b < 4; b++)
                #pragma unroll
                for (int c = 0; c < 4; c++) acc[a][b][c] = 0.f;

        // ---- 12 k16-steps, double-buffered fragments ----
        uint32_t A0[2][4], A1[2][4], Bf[2][2][4];
        load_frags(xb, wb, 0, A0[0], A1[0], Bf[0]);
        #pragma unroll
        for (int s = 0; s < 12; s++) {
            int cur = s & 1, nxt = cur ^ 1;
            if (s < 11)
                load_frags(xb, wb, (uint32_t)(s + 1) * 32,
                           A0[nxt], A1[nxt], Bf[nxt]);
            #pragma unroll
            for (int jj = 0; jj < 2; jj++) {
                mma16816(acc[0][2*jj],     A0[cur], Bf[cur][jj][0], Bf[cur][jj][2]);
                mma16816(acc[0][2*jj + 1], A0[cur], Bf[cur][jj][1], Bf[cur][jj][3]);
                mma16816(acc[1][2*jj],     A1[cur], Bf[cur][jj][0], Bf[cur][jj][2]);
                mma16816(acc[1][2*jj + 1], A1[cur], Bf[cur][jj][1], Bf[cur][jj][3]);
            }
        }

        // ---- bias + relu in registers; per-row partial sums ----
        float ysum[4] = {0.f, 0.f, 0.f, 0.f};
        float yss[4]  = {0.f, 0.f, 0.f, 0.f};
        #pragma unroll
        for (int mf = 0; mf < 2; mf++)
            #pragma unroll
            for (int nf = 0; nf < 4; nf++) {
                int c = c0 + nf * 8;
                float b0 = sPar[c], b1 = sPar[c + 1];
                float v0 = fmaxf(acc[mf][nf][0] + b0, 0.f);
                float v1 = fmaxf(acc[mf][nf][1] + b1, 0.f);
                float v2 = fmaxf(acc[mf][nf][2] + b0, 0.f);
                float v3 = fmaxf(acc[mf][nf][3] + b1, 0.f);
                acc[mf][nf][0] = v0; acc[mf][nf][1] = v1;
                acc[mf][nf][2] = v2; acc[mf][nf][3] = v3;
                ysum[mf*2]     += v0 + v1;
                yss[mf*2]      += v0*v0 + v1*v1;
                ysum[mf*2 + 1] += v2 + v3;
                yss[mf*2 + 1]  += v2*v2 + v3*v3;
            }
        #pragma unroll
        for (int i = 0; i < 4; i++) {
            ysum[i] += __shfl_xor_sync(0xffffffffu, ysum[i], 1);
            ysum[i] += __shfl_xor_sync(0xffffffffu, ysum[i], 2);
            yss[i]  += __shfl_xor_sync(0xffffffffu, yss[i],  1);
            yss[i]  += __shfl_xor_sync(0xffffffffu, yss[i],  2);
        }
        if ((lane & 3) == 0) {
            int r0 = lane >> 2;
            #pragma unroll
            for (int i = 0; i < 4; i++) {
                int r = r0 + (i >> 1) * 16 + (i & 1) * 8;
                sPart[r * 8 + w] = make_float2(ysum[i], yss[i]);
            }
        }
        __syncthreads();

        // ---- finalize LN per row, write out from fragments ----
        #pragma unroll
        for (int i = 0; i < 4; i++) {
            int r = (lane >> 2) + (i >> 1) * 16 + (i & 1) * 8;
            float sum = 0.f, ss = 0.f;
            #pragma unroll
            for (int p = 0; p < 4; p++) {
                float4 pp = *(const float4*)&sPart[r * 8 + p * 2];
                sum += pp.x + pp.z;
                ss  += pp.y + pp.w;
            }
            float mean = sum * (1.f / 256.f);
            float var  = ss * (1.f / 256.f) - mean * mean;
            float rstd = rsqrtf(var + 1e-5f);
            float* orow = out + (size_t)(m_base + r) * CDIM;
            int mf = i >> 1, kp = (i & 1) * 2;
            #pragma unroll
            for (int nf = 0; nf < 4; nf++) {
                int c = c0 + nf * 8;
                float2 o2;
                o2.x = (acc[mf][nf][kp]     - mean) * rstd * sPar[256 + c]     + sPar[512 + c];
                o2.y = (acc[mf][nf][kp + 1] - mean) * rstd * sPar[256 + c + 1] + sPar[512 + c + 1];
                *(float2*)&orow[c] = o2;
            }
        }
        __syncthreads();   // sPart / X buffer safe for next tile
    }
}

// ============================================================
extern "C" void kernel_launch(void* const* d_in, const int* in_sizes, int n_in,
                              void* d_out, int out_size) {
    (void)in_sizes; (void)n_in; (void)out_size;
    const int*   user_input      = (const int*)  d_in[0];
    const float* emb             = (const float*)d_in[1];
    const int*   sc_country_idx  = (const int*)  d_in[2];
    const float* sc_country_emb  = (const float*)d_in[3];
    const int*   sc_device_idx   = (const int*)  d_in[4];
    const float* sc_device_emb   = (const float*)d_in[5];
    const int*   mf_tags_idx     = (const int*)  d_in[6];
    const float* mf_tags_emb     = (const float*)d_in[7];
    const int*   mf_history_idx  = (const int*)  d_in[8];
    const float* mf_history_emb  = (const float*)d_in[9];
    const float* fc_w            = (const float*)d_in[10];
    const float* fc_b            = (const float*)d_in[11];
    const float* ln_g            = (const float*)d_in[12];
    const float* ln_b            = (const float*)d_in[13];
    float* out = (float*)d_out;

    // reset flags on the main (capture) stream
    void* cnt_addr = nullptr;
    cudaGetSymbolAddress(&cnt_addr, g_cnt);
    cudaMemsetAsync(cnt_addr, 0, NTILES * sizeof(int), 0);

    cudaFuncSetAttribute(gemm_ln_mma_kernel,
                         cudaFuncAttributeMaxDynamicSharedMemorySize, SMEM_SZ);

    // fork a second stream so gather and gemm are concurrent graph nodes
    cudaStream_t s2;
    cudaStreamCreateWithFlags(&s2, cudaStreamNonBlocking);
    cudaEvent_t e1, e2;
    cudaEventCreateWithFlags(&e1, cudaEventDisableTiming);
    cudaEventCreateWithFlags(&e2, cudaEventDisableTiming);

    cudaEventRecord(e1, 0);
    cudaStreamWaitEvent(s2, e1, 0);

    gather_kernel<<<GATHER_BLOCKS, 256, 0, s2>>>(
        user_input, emb,
        sc_country_idx, sc_country_emb,
        sc_device_idx,  sc_device_emb,
        mf_tags_idx,    mf_tags_emb,
        mf_history_idx, mf_history_emb);
    cudaEventRecord(e2, s2);

    gemm_ln_mma_kernel<<<GEMM_GRID, GEMM_THREADS, SMEM_SZ, 0>>>(
        fc_w, fc_b, ln_g, ln_b, out);

    cudaStreamWaitEvent(0, e2, 0);   // join

    cudaEventDestroy(e1);
    cudaEventDestroy(e2);
    cudaStreamDestroy(s2);
}